// round 1
// baseline (speedup 1.0000x reference)
#include <cuda_runtime.h>
#include <math.h>

#define BATCH 16
#define CDIM  256
#define NTOK  1024
#define NHEAD 8
#define DH    32
#define HID   1024
#define ROWS  (BATCH*NTOK)          // 16384
#define LN_EPS 1e-5f

// ---------------- scratch (one static device buffer, no allocations) -------
// offsets in floats
#define OFF_XT   0ull                          // (B,n,C)        4,194,304
#define OFF_X1   4194304ull                    // post-LN1       4,194,304
#define OFF_QKV  8388608ull                    // [3][B][H][n][d] 12,582,912
#define OFF_BIAS 20971520ull                   // [H][n][n]      8,388,608
#define OFF_ATT  29360128ull                   // (B,n,C)        4,194,304
#define OFF_X3   33554432ull                   // (B,n,C)        4,194,304
#define OFF_X2   37748736ull                   // (B,n,C)        4,194,304
#define OFF_HID  41943040ull                   // (rows,HID)    16,777,216
#define OFF_Y    58720256ull                   // (B,n,C)        4,194,304
#define SCRATCH_FLOATS 62914560ull             // 240 MB

__device__ float g_scratch[SCRATCH_FLOATS];

// ---------------- transpose: in (B,R,S) -> out (B,S,R) ---------------------
__global__ void transpose_k(const float* __restrict__ in, float* __restrict__ out,
                            int R, int S) {
    __shared__ float tile[32][33];
    int b  = blockIdx.z;
    int s0 = blockIdx.x * 32;
    int r0 = blockIdx.y * 32;
    const float* inb  = in  + (size_t)b * R * S;
    float*       outb = out + (size_t)b * R * S;
    #pragma unroll
    for (int i = threadIdx.y; i < 32; i += 8) {
        tile[i][threadIdx.x] = inb[(size_t)(r0 + i) * S + s0 + threadIdx.x];
    }
    __syncthreads();
    #pragma unroll
    for (int i = threadIdx.y; i < 32; i += 8) {
        outb[(size_t)(s0 + i) * R + r0 + threadIdx.x] = tile[threadIdx.x][i];
    }
}

// ---------------- layernorm over C=256 (1 block per row) -------------------
__global__ void ln_k(const float* __restrict__ in, const float* __restrict__ w,
                     const float* __restrict__ bb, float* __restrict__ outp) {
    __shared__ float red[8];
    __shared__ float red2[8];
    int row = blockIdx.x;
    int t   = threadIdx.x;
    float v = in[(size_t)row * CDIM + t];

    float s = v;
    #pragma unroll
    for (int off = 16; off; off >>= 1) s += __shfl_xor_sync(0xffffffffu, s, off);
    if ((t & 31) == 0) red[t >> 5] = s;
    __syncthreads();
    float mu = 0.f;
    #pragma unroll
    for (int i = 0; i < 8; i++) mu += red[i];
    mu *= (1.0f / CDIM);

    float d  = v - mu;
    float s2 = d * d;
    #pragma unroll
    for (int off = 16; off; off >>= 1) s2 += __shfl_xor_sync(0xffffffffu, s2, off);
    if ((t & 31) == 0) red2[t >> 5] = s2;
    __syncthreads();
    float var = 0.f;
    #pragma unroll
    for (int i = 0; i < 8; i++) var += red2[i];
    var *= (1.0f / CDIM);

    outp[(size_t)row * CDIM + t] = d * rsqrtf(var + LN_EPS) * w[t] + bb[t];
}

// ---------------- bias matrix precompute: bias[h][i*n+j] -------------------
__global__ void bias_k(const int* __restrict__ rel, const float* __restrict__ tab,
                       float* __restrict__ bm) {
    int idx = blockIdx.x * 256 + threadIdx.x;   // 0 .. n*n-1
    int r   = rel[idx];
    #pragma unroll
    for (int h = 0; h < NHEAD; h++)
        bm[(size_t)h * (NTOK * NTOK) + idx] = tab[r * NHEAD + h];
}

// ---------------- SGEMM 128x128x8, 8x8/thread, fused epilogues -------------
// mode 0: scatter into qkv [seg][b][h][t][d]
// mode 1: +bias[c] +resid[r*N+c]
// mode 2: +bias[c] then exact GELU
__global__ __launch_bounds__(256) void sgemm_k(
    const float* __restrict__ A, const float* __restrict__ Bw,
    float* __restrict__ Cout, int M, int N, int K, int mode,
    const float* __restrict__ bias, const float* __restrict__ resid) {

    __shared__ float As[8][128];
    __shared__ float Bs[8][128];

    int bm = blockIdx.y * 128;
    int bn = blockIdx.x * 128;
    int tid = threadIdx.x;
    int tr = tid >> 4;          // 0..15
    int tc = tid & 15;          // 0..15

    float acc[8][8];
    #pragma unroll
    for (int i = 0; i < 8; i++)
        #pragma unroll
        for (int j = 0; j < 8; j++) acc[i][j] = 0.f;

    int aRow = tid >> 1;            // 0..127
    int aCol = (tid & 1) * 4;       // 0 or 4
    int bRow = tid >> 5;            // 0..7
    int bCol = (tid & 31) * 4;      // 0..124

    const float* Aptr = A  + (size_t)(bm + aRow) * K + aCol;
    const float* Bptr = Bw + (size_t)bRow * N + bn + bCol;

    for (int k0 = 0; k0 < K; k0 += 8) {
        float4 a = *(const float4*)(Aptr + k0);
        As[aCol + 0][aRow] = a.x;
        As[aCol + 1][aRow] = a.y;
        As[aCol + 2][aRow] = a.z;
        As[aCol + 3][aRow] = a.w;
        *(float4*)&Bs[bRow][bCol] = *(const float4*)(Bptr + (size_t)k0 * N);
        __syncthreads();

        #pragma unroll
        for (int kk = 0; kk < 8; kk++) {
            float ra[8], rb[8];
            *(float4*)&ra[0] = *(float4*)&As[kk][tr * 8];
            *(float4*)&ra[4] = *(float4*)&As[kk][tr * 8 + 4];
            *(float4*)&rb[0] = *(float4*)&Bs[kk][tc * 8];
            *(float4*)&rb[4] = *(float4*)&Bs[kk][tc * 8 + 4];
            #pragma unroll
            for (int i = 0; i < 8; i++)
                #pragma unroll
                for (int j = 0; j < 8; j++)
                    acc[i][j] = fmaf(ra[i], rb[j], acc[i][j]);
        }
        __syncthreads();
    }

    // epilogue
    #pragma unroll
    for (int i = 0; i < 8; i++) {
        int r = bm + tr * 8 + i;
        #pragma unroll
        for (int j = 0; j < 8; j++) {
            int c = bn + tc * 8 + j;
            float v = acc[i][j];
            if (mode == 0) {
                int seg = c >> 8;         // 0=q,1=k,2=v
                int cc  = c & 255;
                int hh  = cc >> 5;
                int dd  = cc & 31;
                int bb  = r >> 10;
                int t   = r & 1023;
                Cout[(((size_t)seg * BATCH + bb) * NHEAD + hh) * (NTOK * DH)
                     + (size_t)t * DH + dd] = v;
            } else if (mode == 1) {
                v += bias[c];
                v += resid[(size_t)r * N + c];
                Cout[(size_t)r * N + c] = v;
            } else { // mode 2: GELU exact
                v += bias[c];
                v = 0.5f * v * (1.0f + erff(v * 0.70710678118654752f));
                Cout[(size_t)r * N + c] = v;
            }
        }
    }
}

// ---------------- flash-style attention: BQ=BK=64, d=32 --------------------
// grid: (n/64 = 16, B*H = 128), block 256
__global__ __launch_bounds__(256) void attn_k(
    const float* __restrict__ qkv, const float* __restrict__ biasM,
    float* __restrict__ outp) {

    __shared__ float Qs[64][32];
    __shared__ float Ks[64][33];
    __shared__ float Vs[64][32];
    __shared__ float Ss[64][65];

    int tid = threadIdx.x;
    int bh  = blockIdx.y;
    int h   = bh >> 4;              // h-major for L2 bias reuse
    int b   = bh & 15;
    int q0  = blockIdx.x * 64;

    const float* Q  = qkv + (size_t)(b * NHEAD + h) * (NTOK * DH);
    const float* Kp = Q + (size_t)BATCH * NHEAD * NTOK * DH;
    const float* Vp = Kp + (size_t)BATCH * NHEAD * NTOK * DH;
    const float* biasH = biasM + (size_t)h * NTOK * NTOK;

    // load Q tile
    {
        int i = tid >> 2, c = (tid & 3) * 8;
        *(float4*)&Qs[i][c]     = *(const float4*)&Q[(size_t)(q0 + i) * DH + c];
        *(float4*)&Qs[i][c + 4] = *(const float4*)&Q[(size_t)(q0 + i) * DH + c + 4];
    }

    int ty = tid >> 4, tx = tid & 15;   // S compute: 4x4 micro-tile
    int g  = tid >> 2, sub = tid & 3;   // softmax/PV: row g, dim slice sub

    float m = -1e30f, l = 0.f;
    float o[8];
    #pragma unroll
    for (int i = 0; i < 8; i++) o[i] = 0.f;
    const float scale = 0.17677669529663687f;   // 32^-0.5

    for (int kt = 0; kt < 16; kt++) {
        int k0 = kt * 64;
        // load K (padded, scalar stores) and V (float4)
        {
            int i = tid >> 2, c = (tid & 3) * 8;
            float4 a  = *(const float4*)&Kp[(size_t)(k0 + i) * DH + c];
            float4 a2 = *(const float4*)&Kp[(size_t)(k0 + i) * DH + c + 4];
            Ks[i][c + 0] = a.x;  Ks[i][c + 1] = a.y;
            Ks[i][c + 2] = a.z;  Ks[i][c + 3] = a.w;
            Ks[i][c + 4] = a2.x; Ks[i][c + 5] = a2.y;
            Ks[i][c + 6] = a2.z; Ks[i][c + 7] = a2.w;
            *(float4*)&Vs[i][c]     = *(const float4*)&Vp[(size_t)(k0 + i) * DH + c];
            *(float4*)&Vs[i][c + 4] = *(const float4*)&Vp[(size_t)(k0 + i) * DH + c + 4];
        }
        __syncthreads();

        // S = Q K^T  (4x4 per thread)
        float acc[4][4];
        #pragma unroll
        for (int ii = 0; ii < 4; ii++)
            #pragma unroll
            for (int jj = 0; jj < 4; jj++) acc[ii][jj] = 0.f;
        #pragma unroll 8
        for (int kk = 0; kk < 32; kk++) {
            float qa[4], kb[4];
            #pragma unroll
            for (int ii = 0; ii < 4; ii++) qa[ii] = Qs[ty * 4 + ii][kk];
            #pragma unroll
            for (int jj = 0; jj < 4; jj++) kb[jj] = Ks[tx * 4 + jj][kk];
            #pragma unroll
            for (int ii = 0; ii < 4; ii++)
                #pragma unroll
                for (int jj = 0; jj < 4; jj++)
                    acc[ii][jj] = fmaf(qa[ii], kb[jj], acc[ii][jj]);
        }
        // scale + bias -> Ss
        #pragma unroll
        for (int ii = 0; ii < 4; ii++) {
            #pragma unroll
            for (int jj = 0; jj < 4; jj++) {
                float vv = acc[ii][jj] * scale
                    + biasH[(size_t)(q0 + ty * 4 + ii) * NTOK + k0 + tx * 4 + jj];
                Ss[ty * 4 + ii][tx * 4 + jj] = vv;
            }
        }
        __syncthreads();

        // online softmax on row g (4 threads per row, lanes 4k..4k+3)
        float tmax = -1e30f;
        #pragma unroll
        for (int u = 0; u < 16; u++)
            tmax = fmaxf(tmax, Ss[g][sub + 4 * u]);
        tmax = fmaxf(tmax, __shfl_xor_sync(0xffffffffu, tmax, 1));
        tmax = fmaxf(tmax, __shfl_xor_sync(0xffffffffu, tmax, 2));
        float m_new = fmaxf(m, tmax);
        float alpha = __expf(m - m_new);
        l *= alpha;
        #pragma unroll
        for (int i = 0; i < 8; i++) o[i] *= alpha;

        float ps = 0.f;
        #pragma unroll
        for (int u = 0; u < 16; u++) {
            int j = sub + 4 * u;
            float p = __expf(Ss[g][j] - m_new);
            Ss[g][j] = p;
            ps += p;
        }
        ps += __shfl_xor_sync(0xffffffffu, ps, 1);
        ps += __shfl_xor_sync(0xffffffffu, ps, 2);
        l += ps;
        m = m_new;
        __syncwarp();

        // O += P V
        #pragma unroll 8
        for (int j = 0; j < 64; j++) {
            float p = Ss[g][j];
            float4 v0 = *(const float4*)&Vs[j][sub * 8];
            float4 v1 = *(const float4*)&Vs[j][sub * 8 + 4];
            o[0] = fmaf(p, v0.x, o[0]); o[1] = fmaf(p, v0.y, o[1]);
            o[2] = fmaf(p, v0.z, o[2]); o[3] = fmaf(p, v0.w, o[3]);
            o[4] = fmaf(p, v1.x, o[4]); o[5] = fmaf(p, v1.y, o[5]);
            o[6] = fmaf(p, v1.z, o[6]); o[7] = fmaf(p, v1.w, o[7]);
        }
        __syncthreads();
    }

    float inv = 1.0f / l;
    int row = b * NTOK + q0 + g;
    float4 r0 = make_float4(o[0] * inv, o[1] * inv, o[2] * inv, o[3] * inv);
    float4 r1 = make_float4(o[4] * inv, o[5] * inv, o[6] * inv, o[7] * inv);
    float* dst = outp + (size_t)row * CDIM + h * DH + sub * 8;
    *(float4*)dst       = r0;
    *(float4*)(dst + 4) = r1;
}

// ---------------- launcher -------------------------------------------------
extern "C" void kernel_launch(void* const* d_in, const int* in_sizes, int n_in,
                              void* d_out, int out_size) {
    const float* x       = (const float*)d_in[0];
    const float* qkv_w   = (const float*)d_in[1];
    const float* proj_w  = (const float*)d_in[2];
    const float* proj_b  = (const float*)d_in[3];
    const float* ffn_w1  = (const float*)d_in[4];
    const float* ffn_b1  = (const float*)d_in[5];
    const float* ffn_w2  = (const float*)d_in[6];
    const float* ffn_b2  = (const float*)d_in[7];
    const float* n1w     = (const float*)d_in[8];
    const float* n1b     = (const float*)d_in[9];
    const float* n2w     = (const float*)d_in[10];
    const float* n2b     = (const float*)d_in[11];
    const float* btab    = (const float*)d_in[12];
    const int*   relidx  = (const int*)d_in[13];
    float* out = (float*)d_out;

    float* scratch = nullptr;
    cudaGetSymbolAddress((void**)&scratch, g_scratch);
    float* xt    = scratch + OFF_XT;
    float* x1    = scratch + OFF_X1;
    float* qkv   = scratch + OFF_QKV;
    float* biasM = scratch + OFF_BIAS;
    float* att   = scratch + OFF_ATT;
    float* x3    = scratch + OFF_X3;
    float* x2    = scratch + OFF_X2;
    float* hid   = scratch + OFF_HID;
    float* y     = scratch + OFF_Y;

    // 1. x (B,C,n) -> xt (B,n,C)
    transpose_k<<<dim3(32, 8, BATCH), dim3(32, 8)>>>(x, xt, CDIM, NTOK);
    // 2. LN1
    ln_k<<<ROWS, 256>>>(xt, n1w, n1b, x1);
    // 3. bias matrix precompute
    bias_k<<<(NTOK * NTOK) / 256, 256>>>(relidx, btab, biasM);
    // 4. QKV gemm (16384 x 768 x 256), scatter to [seg][b][h][t][d]
    sgemm_k<<<dim3(768 / 128, ROWS / 128), 256>>>(x1, qkv_w, qkv,
                                                  ROWS, 768, CDIM, 0, nullptr, nullptr);
    // 5. attention
    attn_k<<<dim3(NTOK / 64, BATCH * NHEAD), 256>>>(qkv, biasM, att);
    // 6. proj gemm + bias + residual(xt) -> x3 (B,n,C)
    sgemm_k<<<dim3(CDIM / 128, ROWS / 128), 256>>>(att, proj_w, x3,
                                                   ROWS, CDIM, CDIM, 1, proj_b, xt);
    // 7. LN2
    ln_k<<<ROWS, 256>>>(x3, n2w, n2b, x2);
    // 8. FFN1 + GELU
    sgemm_k<<<dim3(HID / 128, ROWS / 128), 256>>>(x2, ffn_w1, hid,
                                                  ROWS, HID, CDIM, 2, ffn_b1, nullptr);
    // 9. FFN2 + bias + residual(x3) -> y (B,n,C)
    sgemm_k<<<dim3(CDIM / 128, ROWS / 128), 256>>>(hid, ffn_w2, y,
                                                   ROWS, CDIM, HID, 1, ffn_b2, x3);
    // 10. y (B,n,C) -> out (B,C,n)
    transpose_k<<<dim3(8, 32, BATCH), dim3(32, 8)>>>(y, out, NTOK, CDIM);
}

// round 2
// speedup vs baseline: 2.3529x; 2.3529x over previous
#include <cuda_runtime.h>
#include <math.h>
#include <stdint.h>

#define BATCH 16
#define CDIM  256
#define NTOK  1024
#define NHEAD 8
#define DH    32
#define HID   1024
#define ROWS  (BATCH*NTOK)          // 16384
#define LN_EPS 1e-5f

// ---------------- scratch (one static device buffer, no allocations) -------
#define OFF_XT   0ull
#define OFF_X1   4194304ull
#define OFF_QKV  8388608ull
#define OFF_BIAS 20971520ull
#define OFF_ATT  29360128ull
#define OFF_X3   33554432ull
#define OFF_X2   37748736ull
#define OFF_HID  41943040ull
#define OFF_Y    58720256ull
#define SCRATCH_FLOATS 62914560ull             // 240 MB

__device__ float g_scratch[SCRATCH_FLOATS];

// ---------------- helpers ---------------------------------------------------
__device__ __forceinline__ float f2tf32(float x) {
    uint32_t u;
    asm("cvt.rna.tf32.f32 %0, %1;" : "=r"(u) : "f"(x));
    return __uint_as_float(u);
}

__device__ __forceinline__ void mma_tf32(float c[4],
                                         const uint32_t a[4],
                                         const uint32_t b[2]) {
    asm volatile(
        "mma.sync.aligned.m16n8k8.row.col.f32.tf32.tf32.f32 "
        "{%0,%1,%2,%3}, {%4,%5,%6,%7}, {%8,%9}, {%0,%1,%2,%3};"
        : "+f"(c[0]), "+f"(c[1]), "+f"(c[2]), "+f"(c[3])
        : "r"(a[0]), "r"(a[1]), "r"(a[2]), "r"(a[3]),
          "r"(b[0]), "r"(b[1]));
}

// ---------------- transpose: in (B,R,S) -> out (B,S,R) ---------------------
__global__ void transpose_k(const float* __restrict__ in, float* __restrict__ out,
                            int R, int S) {
    __shared__ float tile[32][33];
    int b  = blockIdx.z;
    int s0 = blockIdx.x * 32;
    int r0 = blockIdx.y * 32;
    const float* inb  = in  + (size_t)b * R * S;
    float*       outb = out + (size_t)b * R * S;
    #pragma unroll
    for (int i = threadIdx.y; i < 32; i += 8)
        tile[i][threadIdx.x] = inb[(size_t)(r0 + i) * S + s0 + threadIdx.x];
    __syncthreads();
    #pragma unroll
    for (int i = threadIdx.y; i < 32; i += 8)
        outb[(size_t)(s0 + i) * R + r0 + threadIdx.x] = tile[threadIdx.x][i];
}

// ---------------- layernorm over C=256 (1 block per row) -------------------
__global__ void ln_k(const float* __restrict__ in, const float* __restrict__ w,
                     const float* __restrict__ bb, float* __restrict__ outp) {
    __shared__ float red[8];
    __shared__ float red2[8];
    int row = blockIdx.x;
    int t   = threadIdx.x;
    float v = in[(size_t)row * CDIM + t];

    float s = v;
    #pragma unroll
    for (int off = 16; off; off >>= 1) s += __shfl_xor_sync(0xffffffffu, s, off);
    if ((t & 31) == 0) red[t >> 5] = s;
    __syncthreads();
    float mu = 0.f;
    #pragma unroll
    for (int i = 0; i < 8; i++) mu += red[i];
    mu *= (1.0f / CDIM);

    float d  = v - mu;
    float s2 = d * d;
    #pragma unroll
    for (int off = 16; off; off >>= 1) s2 += __shfl_xor_sync(0xffffffffu, s2, off);
    if ((t & 31) == 0) red2[t >> 5] = s2;
    __syncthreads();
    float var = 0.f;
    #pragma unroll
    for (int i = 0; i < 8; i++) var += red2[i];
    var *= (1.0f / CDIM);

    outp[(size_t)row * CDIM + t] = d * rsqrtf(var + LN_EPS) * w[t] + bb[t];
}

// ---------------- bias matrix precompute: bias[h][i*n+j] -------------------
__global__ void bias_k(const int* __restrict__ rel, const float* __restrict__ tab,
                       float* __restrict__ bm) {
    int idx = blockIdx.x * 256 + threadIdx.x;
    int r   = rel[idx];
    #pragma unroll
    for (int h = 0; h < NHEAD; h++)
        bm[(size_t)h * (NTOK * NTOK) + idx] = tab[r * NHEAD + h];
}

// ---------------- TF32 tensor-core GEMM 128x128, K-chunk 32 ----------------
// 8 warps (2x4), each warp 64x32 via 4x4 m16n8k8 tiles.
// mode 0: scatter into qkv [seg][b][h][t][d]
// mode 1: +bias[c] +resid -> C
// mode 2: +bias[c] then exact GELU
__global__ __launch_bounds__(256) void gemm_tf32_k(
    const float* __restrict__ A, const float* __restrict__ Bw,
    float* __restrict__ Cout, int M, int N, int K, int mode,
    const float* __restrict__ bias, const float* __restrict__ resid) {

    __shared__ float As[128][36];   // padded: frag loads conflict-free
    __shared__ float Bs[32][136];

    int tid  = threadIdx.x;
    int bm   = blockIdx.y * 128;
    int bn   = blockIdx.x * 128;
    int warp = tid >> 5, lane = tid & 31;
    int wm   = (warp >> 2) * 64;    // warp M offset (0,64)
    int wn   = (warp & 3) * 32;     // warp N offset (0..96)
    int qr   = lane >> 2;           // 0..7
    int qc   = lane & 3;            // 0..3

    float c[4][4][4];
    #pragma unroll
    for (int mt = 0; mt < 4; mt++)
        #pragma unroll
        for (int nt = 0; nt < 4; nt++)
            #pragma unroll
            for (int x = 0; x < 4; x++) c[mt][nt][x] = 0.f;

    for (int k0 = 0; k0 < K; k0 += 32) {
        // load A tile 128x32 (1024 float4, 4 per thread), convert to tf32
        #pragma unroll
        for (int i = 0; i < 4; i++) {
            int id = tid + i * 256;
            int r  = id >> 3;
            int cc = (id & 7) * 4;
            float4 v = *(const float4*)(A + (size_t)(bm + r) * K + k0 + cc);
            As[r][cc + 0] = f2tf32(v.x);
            As[r][cc + 1] = f2tf32(v.y);
            As[r][cc + 2] = f2tf32(v.z);
            As[r][cc + 3] = f2tf32(v.w);
        }
        // load B tile 32x128
        #pragma unroll
        for (int i = 0; i < 4; i++) {
            int id = tid + i * 256;
            int r  = id >> 5;
            int cc = (id & 31) * 4;
            float4 v = *(const float4*)(Bw + (size_t)(k0 + r) * N + bn + cc);
            Bs[r][cc + 0] = f2tf32(v.x);
            Bs[r][cc + 1] = f2tf32(v.y);
            Bs[r][cc + 2] = f2tf32(v.z);
            Bs[r][cc + 3] = f2tf32(v.w);
        }
        __syncthreads();

        #pragma unroll
        for (int ks = 0; ks < 4; ks++) {
            int kk = ks * 8;
            uint32_t af[4][4], bf[4][2];
            #pragma unroll
            for (int mt = 0; mt < 4; mt++) {
                af[mt][0] = __float_as_uint(As[wm + mt * 16 + qr][kk + qc]);
                af[mt][1] = __float_as_uint(As[wm + mt * 16 + qr + 8][kk + qc]);
                af[mt][2] = __float_as_uint(As[wm + mt * 16 + qr][kk + qc + 4]);
                af[mt][3] = __float_as_uint(As[wm + mt * 16 + qr + 8][kk + qc + 4]);
            }
            #pragma unroll
            for (int nt = 0; nt < 4; nt++) {
                bf[nt][0] = __float_as_uint(Bs[kk + qc][wn + nt * 8 + qr]);
                bf[nt][1] = __float_as_uint(Bs[kk + qc + 4][wn + nt * 8 + qr]);
            }
            #pragma unroll
            for (int mt = 0; mt < 4; mt++)
                #pragma unroll
                for (int nt = 0; nt < 4; nt++)
                    mma_tf32(c[mt][nt], af[mt], bf[nt]);
        }
        __syncthreads();
    }

    // epilogue: pairs (col, col+1) per accumulator half -> float2 ops
    #pragma unroll
    for (int mt = 0; mt < 4; mt++) {
        #pragma unroll
        for (int x2 = 0; x2 < 2; x2++) {
            int r = bm + wm + mt * 16 + qr + x2 * 8;
            #pragma unroll
            for (int nt = 0; nt < 4; nt++) {
                int col = bn + wn + nt * 8 + qc * 2;   // even
                float v0 = c[mt][nt][x2 * 2 + 0];
                float v1 = c[mt][nt][x2 * 2 + 1];
                if (mode == 0) {
                    int seg = col >> 8;
                    int cc  = col & 255;
                    int hh  = cc >> 5;
                    int dd  = cc & 31;      // even, pair stays in same head
                    int b   = r >> 10;
                    int t   = r & 1023;
                    float* dst = Cout + (((size_t)seg * BATCH + b) * NHEAD + hh) * (NTOK * DH)
                                 + (size_t)t * DH + dd;
                    *(float2*)dst = make_float2(v0, v1);
                } else if (mode == 1) {
                    float2 bi = *(const float2*)(bias + col);
                    float2 rs = *(const float2*)(resid + (size_t)r * N + col);
                    *(float2*)(Cout + (size_t)r * N + col) =
                        make_float2(v0 + bi.x + rs.x, v1 + bi.y + rs.y);
                } else {
                    float2 bi = *(const float2*)(bias + col);
                    float a0 = v0 + bi.x, a1 = v1 + bi.y;
                    a0 = 0.5f * a0 * (1.0f + erff(a0 * 0.70710678118654752f));
                    a1 = 0.5f * a1 * (1.0f + erff(a1 * 0.70710678118654752f));
                    *(float2*)(Cout + (size_t)r * N + col) = make_float2(a0, a1);
                }
            }
        }
    }
}

// ---------------- flash-style attention: BQ=BK=64, d=32 --------------------
__global__ __launch_bounds__(256) void attn_k(
    const float* __restrict__ qkv, const float* __restrict__ biasM,
    float* __restrict__ outp) {

    __shared__ float Qs[64][32];
    __shared__ float Ks[64][33];
    __shared__ float Vs[64][32];
    __shared__ float Ss[64][65];

    int tid = threadIdx.x;
    int bh  = blockIdx.y;
    int h   = bh >> 4;
    int b   = bh & 15;
    int q0  = blockIdx.x * 64;

    const float* Q  = qkv + (size_t)(b * NHEAD + h) * (NTOK * DH);
    const float* Kp = Q + (size_t)BATCH * NHEAD * NTOK * DH;
    const float* Vp = Kp + (size_t)BATCH * NHEAD * NTOK * DH;
    const float* biasH = biasM + (size_t)h * NTOK * NTOK;

    {
        int i = tid >> 2, cc = (tid & 3) * 8;
        *(float4*)&Qs[i][cc]     = *(const float4*)&Q[(size_t)(q0 + i) * DH + cc];
        *(float4*)&Qs[i][cc + 4] = *(const float4*)&Q[(size_t)(q0 + i) * DH + cc + 4];
    }

    int ty = tid >> 4, tx = tid & 15;
    int g  = tid >> 2, sub = tid & 3;

    float m = -1e30f, l = 0.f;
    float o[8];
    #pragma unroll
    for (int i = 0; i < 8; i++) o[i] = 0.f;
    const float scale = 0.17677669529663687f;

    for (int kt = 0; kt < 16; kt++) {
        int k0 = kt * 64;
        {
            int i = tid >> 2, cc = (tid & 3) * 8;
            float4 a  = *(const float4*)&Kp[(size_t)(k0 + i) * DH + cc];
            float4 a2 = *(const float4*)&Kp[(size_t)(k0 + i) * DH + cc + 4];
            Ks[i][cc + 0] = a.x;  Ks[i][cc + 1] = a.y;
            Ks[i][cc + 2] = a.z;  Ks[i][cc + 3] = a.w;
            Ks[i][cc + 4] = a2.x; Ks[i][cc + 5] = a2.y;
            Ks[i][cc + 6] = a2.z; Ks[i][cc + 7] = a2.w;
            *(float4*)&Vs[i][cc]     = *(const float4*)&Vp[(size_t)(k0 + i) * DH + cc];
            *(float4*)&Vs[i][cc + 4] = *(const float4*)&Vp[(size_t)(k0 + i) * DH + cc + 4];
        }
        __syncthreads();

        float acc[4][4];
        #pragma unroll
        for (int ii = 0; ii < 4; ii++)
            #pragma unroll
            for (int jj = 0; jj < 4; jj++) acc[ii][jj] = 0.f;
        #pragma unroll 8
        for (int kk = 0; kk < 32; kk++) {
            float qa[4], kb[4];
            #pragma unroll
            for (int ii = 0; ii < 4; ii++) qa[ii] = Qs[ty * 4 + ii][kk];
            #pragma unroll
            for (int jj = 0; jj < 4; jj++) kb[jj] = Ks[tx * 4 + jj][kk];
            #pragma unroll
            for (int ii = 0; ii < 4; ii++)
                #pragma unroll
                for (int jj = 0; jj < 4; jj++)
                    acc[ii][jj] = fmaf(qa[ii], kb[jj], acc[ii][jj]);
        }
        #pragma unroll
        for (int ii = 0; ii < 4; ii++)
            #pragma unroll
            for (int jj = 0; jj < 4; jj++)
                Ss[ty * 4 + ii][tx * 4 + jj] = acc[ii][jj] * scale
                    + biasH[(size_t)(q0 + ty * 4 + ii) * NTOK + k0 + tx * 4 + jj];
        __syncthreads();

        float tmax = -1e30f;
        #pragma unroll
        for (int u = 0; u < 16; u++)
            tmax = fmaxf(tmax, Ss[g][sub + 4 * u]);
        tmax = fmaxf(tmax, __shfl_xor_sync(0xffffffffu, tmax, 1));
        tmax = fmaxf(tmax, __shfl_xor_sync(0xffffffffu, tmax, 2));
        float m_new = fmaxf(m, tmax);
        float alpha = __expf(m - m_new);
        l *= alpha;
        #pragma unroll
        for (int i = 0; i < 8; i++) o[i] *= alpha;

        float ps = 0.f;
        #pragma unroll
        for (int u = 0; u < 16; u++) {
            int j = sub + 4 * u;
            float p = __expf(Ss[g][j] - m_new);
            Ss[g][j] = p;
            ps += p;
        }
        ps += __shfl_xor_sync(0xffffffffu, ps, 1);
        ps += __shfl_xor_sync(0xffffffffu, ps, 2);
        l += ps;
        m = m_new;
        __syncwarp();

        #pragma unroll 8
        for (int j = 0; j < 64; j++) {
            float p = Ss[g][j];
            float4 v0 = *(const float4*)&Vs[j][sub * 8];
            float4 v1 = *(const float4*)&Vs[j][sub * 8 + 4];
            o[0] = fmaf(p, v0.x, o[0]); o[1] = fmaf(p, v0.y, o[1]);
            o[2] = fmaf(p, v0.z, o[2]); o[3] = fmaf(p, v0.w, o[3]);
            o[4] = fmaf(p, v1.x, o[4]); o[5] = fmaf(p, v1.y, o[5]);
            o[6] = fmaf(p, v1.z, o[6]); o[7] = fmaf(p, v1.w, o[7]);
        }
        __syncthreads();
    }

    float inv = 1.0f / l;
    int row = b * NTOK + q0 + g;
    float* dst = outp + (size_t)row * CDIM + h * DH + sub * 8;
    *(float4*)dst       = make_float4(o[0]*inv, o[1]*inv, o[2]*inv, o[3]*inv);
    *(float4*)(dst + 4) = make_float4(o[4]*inv, o[5]*inv, o[6]*inv, o[7]*inv);
}

// ---------------- launcher -------------------------------------------------
extern "C" void kernel_launch(void* const* d_in, const int* in_sizes, int n_in,
                              void* d_out, int out_size) {
    const float* x       = (const float*)d_in[0];
    const float* qkv_w   = (const float*)d_in[1];
    const float* proj_w  = (const float*)d_in[2];
    const float* proj_b  = (const float*)d_in[3];
    const float* ffn_w1  = (const float*)d_in[4];
    const float* ffn_b1  = (const float*)d_in[5];
    const float* ffn_w2  = (const float*)d_in[6];
    const float* ffn_b2  = (const float*)d_in[7];
    const float* n1w     = (const float*)d_in[8];
    const float* n1b     = (const float*)d_in[9];
    const float* n2w     = (const float*)d_in[10];
    const float* n2b     = (const float*)d_in[11];
    const float* btab    = (const float*)d_in[12];
    const int*   relidx  = (const int*)d_in[13];
    float* out = (float*)d_out;

    float* scratch = nullptr;
    cudaGetSymbolAddress((void**)&scratch, g_scratch);
    float* xt    = scratch + OFF_XT;
    float* x1    = scratch + OFF_X1;
    float* qkv   = scratch + OFF_QKV;
    float* biasM = scratch + OFF_BIAS;
    float* att   = scratch + OFF_ATT;
    float* x3    = scratch + OFF_X3;
    float* x2    = scratch + OFF_X2;
    float* hid   = scratch + OFF_HID;
    float* y     = scratch + OFF_Y;

    transpose_k<<<dim3(32, 8, BATCH), dim3(32, 8)>>>(x, xt, CDIM, NTOK);
    ln_k<<<ROWS, 256>>>(xt, n1w, n1b, x1);
    bias_k<<<(NTOK * NTOK) / 256, 256>>>(relidx, btab, biasM);

    gemm_tf32_k<<<dim3(768 / 128, ROWS / 128), 256>>>(x1, qkv_w, qkv,
                                                      ROWS, 768, CDIM, 0, nullptr, nullptr);
    attn_k<<<dim3(NTOK / 64, BATCH * NHEAD), 256>>>(qkv, biasM, att);
    gemm_tf32_k<<<dim3(CDIM / 128, ROWS / 128), 256>>>(att, proj_w, x3,
                                                       ROWS, CDIM, CDIM, 1, proj_b, xt);
    ln_k<<<ROWS, 256>>>(x3, n2w, n2b, x2);
    gemm_tf32_k<<<dim3(HID / 128, ROWS / 128), 256>>>(x2, ffn_w1, hid,
                                                      ROWS, HID, CDIM, 2, ffn_b1, nullptr);
    gemm_tf32_k<<<dim3(CDIM / 128, ROWS / 128), 256>>>(hid, ffn_w2, y,
                                                       ROWS, CDIM, HID, 1, ffn_b2, x3);
    transpose_k<<<dim3(8, 32, BATCH), dim3(32, 8)>>>(y, out, NTOK, CDIM);
}

// round 3
// speedup vs baseline: 4.8349x; 2.0549x over previous
#include <cuda_runtime.h>
#include <math.h>
#include <stdint.h>

#define BATCH 16
#define CDIM  256
#define NTOK  1024
#define NHEAD 8
#define DH    32
#define HID   1024
#define ROWS  (BATCH*NTOK)
#define LN_EPS 1e-5f

#define OFF_XT   0ull
#define OFF_X1   4194304ull
#define OFF_QKV  8388608ull
#define OFF_BIAS 20971520ull
#define OFF_ATT  29360128ull
#define OFF_X3   33554432ull
#define OFF_X2   37748736ull
#define OFF_HID  41943040ull
#define OFF_Y    58720256ull
#define SCRATCH_FLOATS 62914560ull

__device__ float g_scratch[SCRATCH_FLOATS];

// ---------------- helpers ---------------------------------------------------
__device__ __forceinline__ float f2tf32(float x) {
    uint32_t u;
    asm("cvt.rna.tf32.f32 %0, %1;" : "=r"(u) : "f"(x));
    return __uint_as_float(u);
}

__device__ __forceinline__ void mma_tf32(float c[4],
                                         const uint32_t a[4],
                                         const uint32_t b[2]) {
    asm volatile(
        "mma.sync.aligned.m16n8k8.row.col.f32.tf32.tf32.f32 "
        "{%0,%1,%2,%3}, {%4,%5,%6,%7}, {%8,%9}, {%0,%1,%2,%3};"
        : "+f"(c[0]), "+f"(c[1]), "+f"(c[2]), "+f"(c[3])
        : "r"(a[0]), "r"(a[1]), "r"(a[2]), "r"(a[3]),
          "r"(b[0]), "r"(b[1]));
}

// ---------------- transpose -------------------------------------------------
__global__ void transpose_k(const float* __restrict__ in, float* __restrict__ out,
                            int R, int S) {
    __shared__ float tile[32][33];
    int b  = blockIdx.z;
    int s0 = blockIdx.x * 32;
    int r0 = blockIdx.y * 32;
    const float* inb  = in  + (size_t)b * R * S;
    float*       outb = out + (size_t)b * R * S;
    #pragma unroll
    for (int i = threadIdx.y; i < 32; i += 8)
        tile[i][threadIdx.x] = inb[(size_t)(r0 + i) * S + s0 + threadIdx.x];
    __syncthreads();
    #pragma unroll
    for (int i = threadIdx.y; i < 32; i += 8)
        outb[(size_t)(s0 + i) * R + r0 + threadIdx.x] = tile[threadIdx.x][i];
}

// ---------------- layernorm -------------------------------------------------
__global__ void ln_k(const float* __restrict__ in, const float* __restrict__ w,
                     const float* __restrict__ bb, float* __restrict__ outp) {
    __shared__ float red[8];
    __shared__ float red2[8];
    int row = blockIdx.x;
    int t   = threadIdx.x;
    float v = in[(size_t)row * CDIM + t];

    float s = v;
    #pragma unroll
    for (int off = 16; off; off >>= 1) s += __shfl_xor_sync(0xffffffffu, s, off);
    if ((t & 31) == 0) red[t >> 5] = s;
    __syncthreads();
    float mu = 0.f;
    #pragma unroll
    for (int i = 0; i < 8; i++) mu += red[i];
    mu *= (1.0f / CDIM);

    float d  = v - mu;
    float s2 = d * d;
    #pragma unroll
    for (int off = 16; off; off >>= 1) s2 += __shfl_xor_sync(0xffffffffu, s2, off);
    if ((t & 31) == 0) red2[t >> 5] = s2;
    __syncthreads();
    float var = 0.f;
    #pragma unroll
    for (int i = 0; i < 8; i++) var += red2[i];
    var *= (1.0f / CDIM);

    outp[(size_t)row * CDIM + t] = d * rsqrtf(var + LN_EPS) * w[t] + bb[t];
}

// ---------------- bias matrix precompute ------------------------------------
__global__ void bias_k(const int* __restrict__ rel, const float* __restrict__ tab,
                       float* __restrict__ bm) {
    int idx = blockIdx.x * 256 + threadIdx.x;
    int r   = rel[idx];
    #pragma unroll
    for (int h = 0; h < NHEAD; h++)
        bm[(size_t)h * (NTOK * NTOK) + idx] = tab[r * NHEAD + h];
}

// ---------------- TF32 GEMM, 128x128, double-buffered k-chunk 16 ------------
__global__ __launch_bounds__(256) void gemm_tf32_k(
    const float* __restrict__ A, const float* __restrict__ Bw,
    float* __restrict__ Cout, int M, int N, int K, int mode,
    const float* __restrict__ bias, const float* __restrict__ resid) {

    __shared__ float As[2][128][20];   // pad 20: frag LDS conflict-free
    __shared__ float Bs[2][16][132];   // pad 132 (=4 mod 32)

    int tid  = threadIdx.x;
    int bm   = blockIdx.y * 128;
    int bn   = blockIdx.x * 128;
    int warp = tid >> 5, lane = tid & 31;
    int wm   = (warp >> 2) * 64;
    int wn   = (warp & 3) * 32;
    int qr   = lane >> 2;
    int qc   = lane & 3;

    float c[4][4][4];
    #pragma unroll
    for (int mt = 0; mt < 4; mt++)
        #pragma unroll
        for (int nt = 0; nt < 4; nt++)
            #pragma unroll
            for (int x = 0; x < 4; x++) c[mt][nt][x] = 0.f;

    int aR = tid >> 2;                  // row for i=0 (i=1 adds 64)
    int aC = (tid & 3) * 4;
    int bR = tid >> 5;                  // row for i=0 (i=1 adds 8)
    int bC = (tid & 31) * 4;

    float4 ra[2], rb[2];

    // prologue: stage k0=0
    #pragma unroll
    for (int i = 0; i < 2; i++) {
        ra[i] = *(const float4*)(A  + (size_t)(bm + aR + i * 64) * K + aC);
        rb[i] = *(const float4*)(Bw + (size_t)(bR + i * 8) * N + bn + bC);
    }
    #pragma unroll
    for (int i = 0; i < 2; i++) {
        As[0][aR + i * 64][aC + 0] = f2tf32(ra[i].x);
        As[0][aR + i * 64][aC + 1] = f2tf32(ra[i].y);
        As[0][aR + i * 64][aC + 2] = f2tf32(ra[i].z);
        As[0][aR + i * 64][aC + 3] = f2tf32(ra[i].w);
        Bs[0][bR + i * 8][bC + 0] = f2tf32(rb[i].x);
        Bs[0][bR + i * 8][bC + 1] = f2tf32(rb[i].y);
        Bs[0][bR + i * 8][bC + 2] = f2tf32(rb[i].z);
        Bs[0][bR + i * 8][bC + 3] = f2tf32(rb[i].w);
    }
    __syncthreads();

    int buf = 0;
    for (int k0 = 0; k0 < K; k0 += 16) {
        bool more = (k0 + 16) < K;
        if (more) {
            int kn = k0 + 16;
            #pragma unroll
            for (int i = 0; i < 2; i++) {
                ra[i] = *(const float4*)(A  + (size_t)(bm + aR + i * 64) * K + kn + aC);
                rb[i] = *(const float4*)(Bw + (size_t)(kn + bR + i * 8) * N + bn + bC);
            }
        }
        #pragma unroll
        for (int ks = 0; ks < 2; ks++) {
            int kk = ks * 8;
            uint32_t af[4][4], bf[4][2];
            #pragma unroll
            for (int mt = 0; mt < 4; mt++) {
                af[mt][0] = __float_as_uint(As[buf][wm + mt * 16 + qr][kk + qc]);
                af[mt][1] = __float_as_uint(As[buf][wm + mt * 16 + qr + 8][kk + qc]);
                af[mt][2] = __float_as_uint(As[buf][wm + mt * 16 + qr][kk + qc + 4]);
                af[mt][3] = __float_as_uint(As[buf][wm + mt * 16 + qr + 8][kk + qc + 4]);
            }
            #pragma unroll
            for (int nt = 0; nt < 4; nt++) {
                bf[nt][0] = __float_as_uint(Bs[buf][kk + qc][wn + nt * 8 + qr]);
                bf[nt][1] = __float_as_uint(Bs[buf][kk + qc + 4][wn + nt * 8 + qr]);
            }
            #pragma unroll
            for (int mt = 0; mt < 4; mt++)
                #pragma unroll
                for (int nt = 0; nt < 4; nt++)
                    mma_tf32(c[mt][nt], af[mt], bf[nt]);
        }
        if (more) {
            int nb = buf ^ 1;
            #pragma unroll
            for (int i = 0; i < 2; i++) {
                As[nb][aR + i * 64][aC + 0] = f2tf32(ra[i].x);
                As[nb][aR + i * 64][aC + 1] = f2tf32(ra[i].y);
                As[nb][aR + i * 64][aC + 2] = f2tf32(ra[i].z);
                As[nb][aR + i * 64][aC + 3] = f2tf32(ra[i].w);
                Bs[nb][bR + i * 8][bC + 0] = f2tf32(rb[i].x);
                Bs[nb][bR + i * 8][bC + 1] = f2tf32(rb[i].y);
                Bs[nb][bR + i * 8][bC + 2] = f2tf32(rb[i].z);
                Bs[nb][bR + i * 8][bC + 3] = f2tf32(rb[i].w);
            }
            __syncthreads();
            buf = nb;
        }
    }

    // epilogue
    #pragma unroll
    for (int mt = 0; mt < 4; mt++) {
        #pragma unroll
        for (int x2 = 0; x2 < 2; x2++) {
            int r = bm + wm + mt * 16 + qr + x2 * 8;
            #pragma unroll
            for (int nt = 0; nt < 4; nt++) {
                int col = bn + wn + nt * 8 + qc * 2;
                float v0 = c[mt][nt][x2 * 2 + 0];
                float v1 = c[mt][nt][x2 * 2 + 1];
                if (mode == 0) {
                    int seg = col >> 8;
                    int cc  = col & 255;
                    int hh  = cc >> 5;
                    int dd  = cc & 31;
                    int b   = r >> 10;
                    int t   = r & 1023;
                    float* dst = Cout + (((size_t)seg * BATCH + b) * NHEAD + hh) * (NTOK * DH)
                                 + (size_t)t * DH + dd;
                    *(float2*)dst = make_float2(v0, v1);
                } else if (mode == 1) {
                    float2 bi = *(const float2*)(bias + col);
                    float2 rs = *(const float2*)(resid + (size_t)r * N + col);
                    *(float2*)(Cout + (size_t)r * N + col) =
                        make_float2(v0 + bi.x + rs.x, v1 + bi.y + rs.y);
                } else {
                    float2 bi = *(const float2*)(bias + col);
                    float a0 = v0 + bi.x, a1 = v1 + bi.y;
                    a0 = 0.5f * a0 * (1.0f + erff(a0 * 0.70710678118654752f));
                    a1 = 0.5f * a1 * (1.0f + erff(a1 * 0.70710678118654752f));
                    *(float2*)(Cout + (size_t)r * N + col) = make_float2(a0, a1);
                }
            }
        }
    }
}

// ---------------- TF32 tensor-core flash attention, BQ=BK=64 ----------------
// 8 warps: wr=warp>>1 (16-row group), wc=warp&1 (col half).
// S phase: warp computes S[wr*16..+15][wc*32..+31]; PV: O[wr*16..+15][wc*16..+15].
__global__ __launch_bounds__(256) void attn_mma_k(
    const float* __restrict__ qkv, const float* __restrict__ biasM,
    float* __restrict__ outp) {

    __shared__ float Qs[64][36];
    __shared__ float Ks[64][36];
    __shared__ float Vs[64][36];
    __shared__ float Ps[64][68];
    __shared__ float mbuf[2][64];
    __shared__ float sbuf[2][64];

    int tid  = threadIdx.x;
    int warp = tid >> 5, lane = tid & 31;
    int qr   = lane >> 2, qc = lane & 3;
    int wr   = warp >> 1, wc = warp & 1;
    int rb0  = wr * 16;

    int bh = blockIdx.y;
    int h  = bh >> 4;
    int b  = bh & 15;
    int q0 = blockIdx.x * 64;

    const float* Q  = qkv + (size_t)(b * NHEAD + h) * (NTOK * DH);
    const float* Kp = Q + (size_t)BATCH * NHEAD * NTOK * DH;
    const float* Vp = Kp + (size_t)BATCH * NHEAD * NTOK * DH;
    const float* biasH = biasM + (size_t)h * NTOK * NTOK + (size_t)q0 * NTOK;

    // load Q (tf32)
    {
        int i = tid >> 2, cc = (tid & 3) * 8;
        float4 v0 = *(const float4*)&Q[(size_t)(q0 + i) * DH + cc];
        float4 v1 = *(const float4*)&Q[(size_t)(q0 + i) * DH + cc + 4];
        Qs[i][cc + 0] = f2tf32(v0.x); Qs[i][cc + 1] = f2tf32(v0.y);
        Qs[i][cc + 2] = f2tf32(v0.z); Qs[i][cc + 3] = f2tf32(v0.w);
        Qs[i][cc + 4] = f2tf32(v1.x); Qs[i][cc + 5] = f2tf32(v1.y);
        Qs[i][cc + 6] = f2tf32(v1.z); Qs[i][cc + 7] = f2tf32(v1.w);
    }

    float m0 = -1e30f, m1 = -1e30f, l0 = 0.f, l1 = 0.f;
    float co[2][4];
    #pragma unroll
    for (int nt = 0; nt < 2; nt++)
        #pragma unroll
        for (int x = 0; x < 4; x++) co[nt][x] = 0.f;

    const float scale = 0.17677669529663687f;

    for (int kt = 0; kt < 16; kt++) {
        int k0 = kt * 64;
        // load K,V tiles (tf32)
        {
            int i = tid >> 2, cc = (tid & 3) * 8;
            float4 a0 = *(const float4*)&Kp[(size_t)(k0 + i) * DH + cc];
            float4 a1 = *(const float4*)&Kp[(size_t)(k0 + i) * DH + cc + 4];
            Ks[i][cc + 0] = f2tf32(a0.x); Ks[i][cc + 1] = f2tf32(a0.y);
            Ks[i][cc + 2] = f2tf32(a0.z); Ks[i][cc + 3] = f2tf32(a0.w);
            Ks[i][cc + 4] = f2tf32(a1.x); Ks[i][cc + 5] = f2tf32(a1.y);
            Ks[i][cc + 6] = f2tf32(a1.z); Ks[i][cc + 7] = f2tf32(a1.w);
            float4 b0 = *(const float4*)&Vp[(size_t)(k0 + i) * DH + cc];
            float4 b1 = *(const float4*)&Vp[(size_t)(k0 + i) * DH + cc + 4];
            Vs[i][cc + 0] = f2tf32(b0.x); Vs[i][cc + 1] = f2tf32(b0.y);
            Vs[i][cc + 2] = f2tf32(b0.z); Vs[i][cc + 3] = f2tf32(b0.w);
            Vs[i][cc + 4] = f2tf32(b1.x); Vs[i][cc + 5] = f2tf32(b1.y);
            Vs[i][cc + 6] = f2tf32(b1.z); Vs[i][cc + 7] = f2tf32(b1.w);
        }
        __syncthreads();                       // S1: tiles ready

        // S = Q K^T (warp: 16 rows x 32 cols, 4 n-tiles)
        float cs[4][4];
        #pragma unroll
        for (int nt = 0; nt < 4; nt++)
            #pragma unroll
            for (int x = 0; x < 4; x++) cs[nt][x] = 0.f;
        #pragma unroll
        for (int ks = 0; ks < 4; ks++) {
            int kk = ks * 8;
            uint32_t a[4];
            a[0] = __float_as_uint(Qs[rb0 + qr][kk + qc]);
            a[1] = __float_as_uint(Qs[rb0 + qr + 8][kk + qc]);
            a[2] = __float_as_uint(Qs[rb0 + qr][kk + qc + 4]);
            a[3] = __float_as_uint(Qs[rb0 + qr + 8][kk + qc + 4]);
            #pragma unroll
            for (int nt = 0; nt < 4; nt++) {
                uint32_t bf[2];
                int ncol = wc * 32 + nt * 8 + qr;
                bf[0] = __float_as_uint(Ks[ncol][kk + qc]);
                bf[1] = __float_as_uint(Ks[ncol][kk + qc + 4]);
                mma_tf32(cs[nt], a, bf);
            }
        }

        // scale + bias, local row max
        float lm0 = -1e30f, lm1 = -1e30f;
        #pragma unroll
        for (int nt = 0; nt < 4; nt++) {
            int colg = k0 + wc * 32 + nt * 8 + qc * 2;
            float2 b0 = *(const float2*)&biasH[(size_t)(rb0 + qr) * NTOK + colg];
            float2 b1 = *(const float2*)&biasH[(size_t)(rb0 + qr + 8) * NTOK + colg];
            cs[nt][0] = fmaf(cs[nt][0], scale, b0.x);
            cs[nt][1] = fmaf(cs[nt][1], scale, b0.y);
            cs[nt][2] = fmaf(cs[nt][2], scale, b1.x);
            cs[nt][3] = fmaf(cs[nt][3], scale, b1.y);
            lm0 = fmaxf(lm0, fmaxf(cs[nt][0], cs[nt][1]));
            lm1 = fmaxf(lm1, fmaxf(cs[nt][2], cs[nt][3]));
        }
        lm0 = fmaxf(lm0, __shfl_xor_sync(0xffffffffu, lm0, 1));
        lm0 = fmaxf(lm0, __shfl_xor_sync(0xffffffffu, lm0, 2));
        lm1 = fmaxf(lm1, __shfl_xor_sync(0xffffffffu, lm1, 1));
        lm1 = fmaxf(lm1, __shfl_xor_sync(0xffffffffu, lm1, 2));
        if (qc == 0) {
            mbuf[wc][rb0 + qr]     = lm0;
            mbuf[wc][rb0 + qr + 8] = lm1;
        }
        __syncthreads();                       // S2: mbuf ready

        float M0 = fmaxf(mbuf[0][rb0 + qr],     mbuf[1][rb0 + qr]);
        float M1 = fmaxf(mbuf[0][rb0 + qr + 8], mbuf[1][rb0 + qr + 8]);
        float mn0 = fmaxf(m0, M0), mn1 = fmaxf(m1, M1);
        float al0 = __expf(m0 - mn0), al1 = __expf(m1 - mn1);

        // exp, write P (tf32), partial sums
        float ps0 = 0.f, ps1 = 0.f;
        #pragma unroll
        for (int nt = 0; nt < 4; nt++) {
            float p0 = __expf(cs[nt][0] - mn0);
            float p1 = __expf(cs[nt][1] - mn0);
            float p2 = __expf(cs[nt][2] - mn1);
            float p3 = __expf(cs[nt][3] - mn1);
            ps0 += p0 + p1;
            ps1 += p2 + p3;
            int col = wc * 32 + nt * 8 + qc * 2;
            *(float2*)&Ps[rb0 + qr][col]     = make_float2(f2tf32(p0), f2tf32(p1));
            *(float2*)&Ps[rb0 + qr + 8][col] = make_float2(f2tf32(p2), f2tf32(p3));
        }
        ps0 += __shfl_xor_sync(0xffffffffu, ps0, 1);
        ps0 += __shfl_xor_sync(0xffffffffu, ps0, 2);
        ps1 += __shfl_xor_sync(0xffffffffu, ps1, 1);
        ps1 += __shfl_xor_sync(0xffffffffu, ps1, 2);
        if (qc == 0) {
            sbuf[wc][rb0 + qr]     = ps0;
            sbuf[wc][rb0 + qr + 8] = ps1;
        }
        __syncthreads();                       // S3: sbuf + Ps ready

        l0 = l0 * al0 + sbuf[0][rb0 + qr]     + sbuf[1][rb0 + qr];
        l1 = l1 * al1 + sbuf[0][rb0 + qr + 8] + sbuf[1][rb0 + qr + 8];
        m0 = mn0; m1 = mn1;

        // rescale O, then O += P V (warp: 16 rows x 16 cols, 2 n-tiles)
        #pragma unroll
        for (int nt = 0; nt < 2; nt++) {
            co[nt][0] *= al0; co[nt][1] *= al0;
            co[nt][2] *= al1; co[nt][3] *= al1;
        }
        #pragma unroll
        for (int ks = 0; ks < 8; ks++) {
            int kk = ks * 8;
            uint32_t a[4];
            a[0] = __float_as_uint(Ps[rb0 + qr][kk + qc]);
            a[1] = __float_as_uint(Ps[rb0 + qr + 8][kk + qc]);
            a[2] = __float_as_uint(Ps[rb0 + qr][kk + qc + 4]);
            a[3] = __float_as_uint(Ps[rb0 + qr + 8][kk + qc + 4]);
            #pragma unroll
            for (int nt = 0; nt < 2; nt++) {
                uint32_t bf[2];
                int ncol = wc * 16 + nt * 8 + qr;
                bf[0] = __float_as_uint(Vs[kk + qc][ncol]);
                bf[1] = __float_as_uint(Vs[kk + qc + 4][ncol]);
                mma_tf32(co[nt], a, bf);
            }
        }
        __syncthreads();                       // S4: done reading Ks/Vs/Ps
    }

    float inv0 = 1.0f / l0, inv1 = 1.0f / l1;
    int row0 = b * NTOK + q0 + rb0 + qr;
    #pragma unroll
    for (int nt = 0; nt < 2; nt++) {
        int col = h * DH + wc * 16 + nt * 8 + qc * 2;
        *(float2*)&outp[(size_t)row0 * CDIM + col] =
            make_float2(co[nt][0] * inv0, co[nt][1] * inv0);
        *(float2*)&outp[(size_t)(row0 + 8) * CDIM + col] =
            make_float2(co[nt][2] * inv1, co[nt][3] * inv1);
    }
}

// ---------------- launcher -------------------------------------------------
extern "C" void kernel_launch(void* const* d_in, const int* in_sizes, int n_in,
                              void* d_out, int out_size) {
    const float* x       = (const float*)d_in[0];
    const float* qkv_w   = (const float*)d_in[1];
    const float* proj_w  = (const float*)d_in[2];
    const float* proj_b  = (const float*)d_in[3];
    const float* ffn_w1  = (const float*)d_in[4];
    const float* ffn_b1  = (const float*)d_in[5];
    const float* ffn_w2  = (const float*)d_in[6];
    const float* ffn_b2  = (const float*)d_in[7];
    const float* n1w     = (const float*)d_in[8];
    const float* n1b     = (const float*)d_in[9];
    const float* n2w     = (const float*)d_in[10];
    const float* n2b     = (const float*)d_in[11];
    const float* btab    = (const float*)d_in[12];
    const int*   relidx  = (const int*)d_in[13];
    float* out = (float*)d_out;

    float* scratch = nullptr;
    cudaGetSymbolAddress((void**)&scratch, g_scratch);
    float* xt    = scratch + OFF_XT;
    float* x1    = scratch + OFF_X1;
    float* qkv   = scratch + OFF_QKV;
    float* biasM = scratch + OFF_BIAS;
    float* att   = scratch + OFF_ATT;
    float* x3    = scratch + OFF_X3;
    float* x2    = scratch + OFF_X2;
    float* hid   = scratch + OFF_HID;
    float* y     = scratch + OFF_Y;

    transpose_k<<<dim3(32, 8, BATCH), dim3(32, 8)>>>(x, xt, CDIM, NTOK);
    ln_k<<<ROWS, 256>>>(xt, n1w, n1b, x1);
    bias_k<<<(NTOK * NTOK) / 256, 256>>>(relidx, btab, biasM);

    gemm_tf32_k<<<dim3(768 / 128, ROWS / 128), 256>>>(x1, qkv_w, qkv,
                                                      ROWS, 768, CDIM, 0, nullptr, nullptr);
    attn_mma_k<<<dim3(NTOK / 64, BATCH * NHEAD), 256>>>(qkv, biasM, att);
    gemm_tf32_k<<<dim3(CDIM / 128, ROWS / 128), 256>>>(att, proj_w, x3,
                                                       ROWS, CDIM, CDIM, 1, proj_b, xt);
    ln_k<<<ROWS, 256>>>(x3, n2w, n2b, x2);
    gemm_tf32_k<<<dim3(HID / 128, ROWS / 128), 256>>>(x2, ffn_w1, hid,
                                                      ROWS, HID, CDIM, 2, ffn_b1, nullptr);
    gemm_tf32_k<<<dim3(CDIM / 128, ROWS / 128), 256>>>(hid, ffn_w2, y,
                                                       ROWS, CDIM, HID, 1, ffn_b2, x3);
    transpose_k<<<dim3(8, 32, BATCH), dim3(32, 8)>>>(y, out, NTOK, CDIM);
}